// round 8
// baseline (speedup 1.0000x reference)
#include <cuda_runtime.h>
#include <cuda_bf16.h>
#include <math.h>
#include <stdint.h>

// ---------------------------------------------------------------------------
// VectorQuantizer on B200 (baseline sm_100 target — NO tcgen05/wgmma).
//   x   : [32, 64, 64, 64] float   N = 131072 vectors of dim 64
//   emb : [1024, 64] float
//   out : [loss, z_q (8388608), perplexity]
//
// Phase 1 (mma.sync m16n8k16 bf16->f32): dot[128 pos x 1024 codes].
//   Per-position running max; collect candidates >= prefix_max - MARGIN
//   (conservative superset of the exact argmin).
// Phase 2 (exact fp32, bit-exact reference pipeline):
//   dist = fp32(fp32(zn+en) - 2*dot_fma), argmin with lowest-k ties.
//   Overflow fallback: exact full 128x1024 rescan (deterministic, rare).
// ---------------------------------------------------------------------------

#define KCODES 1024
#define DDIM 64
#define NPOS (32*64*64)
#define TOTAL_ELEMS (NPOS*DDIM)
#define NBLOCKS 1024
#define CAND_CAP 4096
#define MARGIN 3.0e-3f
#define BST 72                     // bf16 row stride (144B): conflict-free frags

// smem byte offsets
#define SM_B      0                                  // emb bf16 [1024][72] = 147456
#define SM_A      147456                             // z bf16 [128][72]    = 18432
#define SM_ZF     165888                             // z fp32 [128][65]    = 33280
#define SM_ZN     199168                             // ||z||^2 [128]       = 512
#define SM_GMAX   199680                             // ordered-uint max [128]
#define SM_MINP   200192                             // packed (dist<<32)|k u64 [128]
#define SM_RED    201216                             // loss reduction [256]
#define SM_CNT    202240                             // candidate count
#define SM_CAND   202256                             // candidates (p<<10)|k
#define SM_TOTAL  (SM_CAND + CAND_CAP*4)             // 218640

__device__ float g_enorm[KCODES];
__device__ int   g_counts[KCODES];
__device__ float g_partial[NBLOCKS];
__device__ __align__(16) unsigned short g_embpad[KCODES * BST];  // bf16, padded

// ---- helpers --------------------------------------------------------------
__device__ __forceinline__ void hmma16816(float* c, const uint32_t* a,
                                          const uint32_t* b) {
    asm volatile(
        "mma.sync.aligned.m16n8k16.row.col.f32.bf16.bf16.f32 "
        "{%0,%1,%2,%3}, {%4,%5,%6,%7}, {%8,%9}, {%0,%1,%2,%3};"
        : "+f"(c[0]), "+f"(c[1]), "+f"(c[2]), "+f"(c[3])
        : "r"(a[0]), "r"(a[1]), "r"(a[2]), "r"(a[3]), "r"(b[0]), "r"(b[1]));
}
// float -> order-preserving uint (ascending)
__device__ __forceinline__ unsigned ford(float f) {
    unsigned u = __float_as_uint(f);
    return (u & 0x80000000u) ? ~u : (u | 0x80000000u);
}
__device__ __forceinline__ float finv(unsigned u) {
    unsigned v = (u & 0x80000000u) ? (u ^ 0x80000000u) : ~u;
    return __uint_as_float(v);
}

// ---------------------------------------------------------------------------
// prep: zero counts, exact ||e||^2 (mul+add sequential), bf16 padded codebook
// ---------------------------------------------------------------------------
__global__ void vq_prep(const float* __restrict__ emb) {
    int gtid = blockIdx.x * blockDim.x + threadIdx.x;   // 2048 threads
    if (gtid < KCODES) {
        g_counts[gtid] = 0;
        float s = 0.0f;
#pragma unroll
        for (int d = 0; d < DDIM; d++) {
            float v = emb[gtid * DDIM + d];
            s = __fadd_rn(s, __fmul_rn(v, v));
        }
        g_enorm[gtid] = s;
    }
    for (int idx = gtid; idx < KCODES * DDIM; idx += 2048) {
        int k = idx >> 6, d = idx & 63;
        g_embpad[k * BST + d] =
            __bfloat16_as_ushort(__float2bfloat16(emb[idx]));
    }
}

// ---------------------------------------------------------------------------
// main: one block = one batch image x 128 positions, all 1024 codes
// ---------------------------------------------------------------------------
extern __shared__ __align__(16) unsigned char smem8[];

__global__ __launch_bounds__(256, 1)
void vq_main(const float* __restrict__ x, const float* __restrict__ emb,
             float* __restrict__ zq_out) {
    const int tid = threadIdx.x;
    const int wid = tid >> 5;
    const int lane = tid & 31;
    const int b = blockIdx.x >> 5;
    const int pos0 = (blockIdx.x & 31) * 128;

    unsigned short* Bsm = (unsigned short*)(smem8 + SM_B);
    unsigned short* Asm = (unsigned short*)(smem8 + SM_A);
    float* zf = (float*)(smem8 + SM_ZF);                  // [128][65]
    float* znsm = (float*)(smem8 + SM_ZN);
    unsigned* gmaxu = (unsigned*)(smem8 + SM_GMAX);
    unsigned long long* minp = (unsigned long long*)(smem8 + SM_MINP);
    float* red = (float*)(smem8 + SM_RED);
    int* candCnt = (int*)(smem8 + SM_CNT);
    unsigned* cand = (unsigned*)(smem8 + SM_CAND);

    if (tid == 0) *candCnt = 0;
    if (tid < 128) { gmaxu[tid] = 0u; minp[tid] = ~0ull; }

    // ---- stage B (bf16 padded codebook) ----
    {
        const uint4* src = (const uint4*)g_embpad;
        uint4* dst = (uint4*)Bsm;
        for (int i = tid; i < (KCODES * BST * 2) / 16; i += 256) dst[i] = src[i];
    }
    // ---- load x -> zf (transpose) ----
    {
        const float* xb = x + (size_t)b * DDIM * 4096 + pos0;
        for (int idx = tid; idx < DDIM * 128; idx += 256) {
            int c = idx >> 7, i = idx & 127;
            zf[i * 65 + c] = xb[c * 4096 + i];
        }
    }
    __syncthreads();

    // ---- z -> bf16 A tile; exact ||z||^2 ----
    {
        int p = tid >> 1, c0 = (tid & 1) * 32;
        const float* zr = &zf[p * 65 + c0];
#pragma unroll
        for (int d = 0; d < 32; d += 2) {
            float flo = zr[d], fhi = zr[d + 1];
            uint32_t pk;
            asm("cvt.rn.bf16x2.f32 %0, %1, %2;" : "=r"(pk) : "f"(fhi), "f"(flo));
            *(uint32_t*)&Asm[p * BST + c0 + d] = pk;
        }
    }
    if (tid < 128) {
        float s = 0.0f;
#pragma unroll
        for (int d = 0; d < DDIM; d++) {
            float v = zf[tid * 65 + d];
            s = __fadd_rn(s, __fmul_rn(v, v));
        }
        znsm[tid] = s;
    }
    __syncthreads();

    // ---- warp-tiled bf16 GEMM + fold ----
    // warp layout: mbase = (wid&3)*32 (2 m-tiles of 16), nbase = (wid>>2)*512
    const int g = lane >> 2, tg = lane & 3;
    const int mbase = (wid & 3) * 32;
    const int nbase = (wid >> 2) * 512;

    uint32_t afrag[2][4][4];
#pragma unroll
    for (int mt = 0; mt < 2; mt++) {
        const int pm = mbase + mt * 16;
#pragma unroll
        for (int kt = 0; kt < 4; kt++) {
            const int kb = kt * 16 + tg * 2;
            afrag[mt][kt][0] = *(const uint32_t*)&Asm[(pm + g) * BST + kb];
            afrag[mt][kt][1] = *(const uint32_t*)&Asm[(pm + g + 8) * BST + kb];
            afrag[mt][kt][2] = *(const uint32_t*)&Asm[(pm + g) * BST + kb + 8];
            afrag[mt][kt][3] = *(const uint32_t*)&Asm[(pm + g + 8) * BST + kb + 8];
        }
    }

    for (int ch = 0; ch < 16; ch++) {                 // 16 chunks x 32 codes
        const int n0c = nbase + ch * 32;
        uint32_t bfrag[4][4][2];
#pragma unroll
        for (int j = 0; j < 4; j++) {
            const int nrow = (n0c + j * 8 + g) * BST;
#pragma unroll
            for (int kt = 0; kt < 4; kt++) {
                const int kb = kt * 16 + tg * 2;
                bfrag[j][kt][0] = *(const uint32_t*)&Bsm[nrow + kb];
                bfrag[j][kt][1] = *(const uint32_t*)&Bsm[nrow + kb + 8];
            }
        }
        float c[2][4][4];
#pragma unroll
        for (int mt = 0; mt < 2; mt++)
#pragma unroll
            for (int j = 0; j < 4; j++) {
#pragma unroll
                for (int q = 0; q < 4; q++) c[mt][j][q] = 0.0f;
#pragma unroll
                for (int kt = 0; kt < 4; kt++)
                    hmma16816(c[mt][j], afrag[mt][kt], bfrag[j][kt]);
            }

        // fold: per-position chunk max -> atomicMax; then candidate scan
#pragma unroll
        for (int mt = 0; mt < 2; mt++) {
            const int plo = mbase + mt * 16 + g, phi = plo + 8;
            float mlo = fmaxf(fmaxf(c[mt][0][0], c[mt][0][1]),
                              fmaxf(c[mt][1][0], c[mt][1][1]));
            mlo = fmaxf(mlo, fmaxf(fmaxf(c[mt][2][0], c[mt][2][1]),
                                   fmaxf(c[mt][3][0], c[mt][3][1])));
            float mhi = fmaxf(fmaxf(c[mt][0][2], c[mt][0][3]),
                              fmaxf(c[mt][1][2], c[mt][1][3]));
            mhi = fmaxf(mhi, fmaxf(fmaxf(c[mt][2][2], c[mt][2][3]),
                                   fmaxf(c[mt][3][2], c[mt][3][3])));
#pragma unroll
            for (int off = 1; off < 4; off <<= 1) {
                mlo = fmaxf(mlo, __shfl_xor_sync(0xffffffffu, mlo, off));
                mhi = fmaxf(mhi, __shfl_xor_sync(0xffffffffu, mhi, off));
            }
            if (tg == 0) {
                atomicMax(&gmaxu[plo], ford(mlo));
                atomicMax(&gmaxu[phi], ford(mhi));
            }
        }
        __syncwarp();
#pragma unroll
        for (int mt = 0; mt < 2; mt++) {
            const int plo = mbase + mt * 16 + g, phi = plo + 8;
            const float tlo = finv(gmaxu[plo]) - MARGIN;
            const float thi = finv(gmaxu[phi]) - MARGIN;
#pragma unroll
            for (int j = 0; j < 4; j++) {
                const int k0 = n0c + j * 8 + tg * 2;
                if (c[mt][j][0] >= tlo) {
                    int s = atomicAdd(candCnt, 1);
                    if (s < CAND_CAP) cand[s] = ((unsigned)plo << 10) | k0;
                }
                if (c[mt][j][1] >= tlo) {
                    int s = atomicAdd(candCnt, 1);
                    if (s < CAND_CAP) cand[s] = ((unsigned)plo << 10) | (k0 + 1);
                }
                if (c[mt][j][2] >= thi) {
                    int s = atomicAdd(candCnt, 1);
                    if (s < CAND_CAP) cand[s] = ((unsigned)phi << 10) | k0;
                }
                if (c[mt][j][3] >= thi) {
                    int s = atomicAdd(candCnt, 1);
                    if (s < CAND_CAP) cand[s] = ((unsigned)phi << 10) | (k0 + 1);
                }
            }
        }
    }
    __syncthreads();

    // ---- exact rescore (bit-exact reference pipeline) ---------------------
    const int cntRaw = *candCnt;
    if (cntRaw <= CAND_CAP) {
        for (int i = tid; i < cntRaw; i += 256) {
            unsigned e = cand[i];
            int cp = e >> 10, ck = e & 1023;
            const float* ek = emb + ck * DDIM;
            const float* zp = &zf[cp * 65];
            float dot = 0.0f;
#pragma unroll
            for (int d = 0; d < DDIM; d++) dot = fmaf(zp[d], ek[d], dot);
            float dist = __fsub_rn(__fadd_rn(znsm[cp], g_enorm[ck]),
                                   __fmul_rn(2.0f, dot));
            unsigned long long pk =
                ((unsigned long long)__float_as_uint(dist) << 32) | (unsigned)ck;
            atomicMin(&minp[cp], pk);
        }
    } else {
        // overflow fallback: exact full rescan (deterministic, ~never taken)
        for (int idx = tid; idx < 128 * 1024; idx += 256) {
            int cp = idx >> 10, ck = idx & 1023;
            const float* ek = emb + ck * DDIM;
            const float* zp = &zf[cp * 65];
            float dot = 0.0f;
#pragma unroll
            for (int d = 0; d < DDIM; d++) dot = fmaf(zp[d], ek[d], dot);
            float dist = __fsub_rn(__fadd_rn(znsm[cp], g_enorm[ck]),
                                   __fmul_rn(2.0f, dot));
            unsigned long long pk =
                ((unsigned long long)__float_as_uint(dist) << 32) | (unsigned)ck;
            atomicMin(&minp[cp], pk);
        }
    }
    __syncthreads();

    if (tid < 128) atomicAdd(&g_counts[(int)(minp[tid] & 1023u)], 1);

    // ---- gather z_q (reuse B region) + loss partial -----------------------
    float* zq = (float*)(smem8 + SM_B);   // [128][65]
    float lsum = 0.0f;
    for (int idx = tid; idx < 128 * DDIM; idx += 256) {
        int pp = idx >> 6, dd = idx & 63;
        int k = (int)(minp[pp] & 1023u);
        float v = emb[k * DDIM + dd];
        zq[pp * 65 + dd] = v;
        float diff = v - zf[pp * 65 + dd];
        lsum = fmaf(diff, diff, lsum);
    }
    red[tid] = lsum;
    __syncthreads();
    for (int st = 128; st > 0; st >>= 1) {
        if (tid < st) red[tid] += red[tid + st];
        __syncthreads();
    }
    if (tid == 0) g_partial[blockIdx.x] = red[0];

    // ---- transposed store: zq_out[b, dd, pos0+p] --------------------------
    float* ob = zq_out + (size_t)b * DDIM * 4096 + pos0;
    for (int idx = tid; idx < DDIM * 128; idx += 256) {
        int dd = idx >> 7, pp = idx & 127;
        ob[dd * 4096 + pp] = zq[pp * 65 + dd];
    }
}

// ---------------------------------------------------------------------------
// finalize: deterministic loss sum + perplexity
// ---------------------------------------------------------------------------
__global__ void vq_finalize(float* __restrict__ out, int out_size) {
    __shared__ double sred[256];
    const int tid = threadIdx.x;

    double s = 0.0;
    for (int i = tid; i < NBLOCKS; i += 256) s += (double)g_partial[i];
    sred[tid] = s;
    __syncthreads();
    for (int st = 128; st > 0; st >>= 1) {
        if (tid < st) sred[tid] += sred[tid + st];
        __syncthreads();
    }
    const double totalLoss = sred[0];
    __syncthreads();

    double e = 0.0;
    for (int i = tid; i < KCODES; i += 256) {
        double p = (double)g_counts[i] / (double)NPOS;
        e += p * log(p + 1e-10);
    }
    sred[tid] = e;
    __syncthreads();
    for (int st = 128; st > 0; st >>= 1) {
        if (tid < st) sred[tid] += sred[tid + st];
        __syncthreads();
    }
    if (tid == 0) {
        out[0] = (float)(1.25 * totalLoss / (double)TOTAL_ELEMS);
        out[out_size - 1] = (float)exp(-sred[0]);
    }
}

// ---------------------------------------------------------------------------
extern "C" void kernel_launch(void* const* d_in, const int* in_sizes, int n_in,
                              void* d_out, int out_size) {
    const float* x = (const float*)d_in[0];
    const float* emb = (const float*)d_in[1];
    if (n_in >= 2 && in_sizes[0] == KCODES * DDIM && in_sizes[1] == TOTAL_ELEMS) {
        x = (const float*)d_in[1];
        emb = (const float*)d_in[0];
    }
    float* out = (float*)d_out;
    const bool has_scalars = (out_size > TOTAL_ELEMS + 1);
    float* zq_base = has_scalars ? (out + 1) : out;

    cudaFuncSetAttribute((const void*)vq_main,
                         cudaFuncAttributeMaxDynamicSharedMemorySize, SM_TOTAL);

    vq_prep<<<8, 256>>>(emb);
    vq_main<<<NBLOCKS, 256, SM_TOTAL>>>(x, emb, zq_base);
    if (has_scalars) vq_finalize<<<1, 256>>>(out, out_size);
}